// round 17
// baseline (speedup 1.0000x reference)
#include <cuda_runtime.h>
#include <cuda_bf16.h>

#define NN 320
#define DD 256
#define NB 522   // 200 half-K dist producers + 2 sort + 320 consumers

// Scratch (allocation-free device globals)
__device__ float  g_D0[NN * NN];  // K-slice 0 partial squared distances
__device__ float  g_D1[NN * NN];  // K-slice 1 partial squared distances
__device__ float  g_ys[NN];       // sorted y_times
__device__ int    g_perm[NN];     // sorted pos -> original index
__device__ int    g_se[NN];       // event class in sorted order
__device__ int    g_gt[NN];       // per k: count of !(ys-yk > 0)
__device__ int    g_geq[NN];      // per k: count of (ys-yk < 0)
__device__ float  g_S[NN];        // per-anchor logp sums (atomic; zeroed by sort blocks)
__device__ float  g_C[NN];        // per-anchor valid counts (atomic; zeroed by sort blocks)
__device__ int    g_rflag[10];    // per-tile-row completion (monotone, +20/replay)
__device__ int    g_sflag;        // sort completion (monotone, +2/replay)
__device__ int    g_cons;         // consumer tickets (monotone, +320/replay)
__device__ int    g_ctr;          // consumer completion (monotone, +320/replay)

// TABLE rows packed: weight code c in {0,1,2} (weight = c*0.5) at bits [2v+1:2v],
// v = td + 3*e, td in {1(lower),2(middle),3(upper)}.
__constant__ int c_rb[7] = {8852, 5460, 4692, 5460, 5716, 4436, 8852};

typedef unsigned long long ull;

// Packed fp32x2 helpers (sm_103a FFMA2 path — only reachable via PTX).
// acc += (x + ny)^2 elementwise; x + (-y) is IEEE-identical to x - y.
__device__ __forceinline__ void dsq_acc(ull& acc, ull x, ull ny) {
    ull d;
    asm("add.rn.f32x2 %0, %1, %2;" : "=l"(d) : "l"(x), "l"(ny));
    asm("fma.rn.f32x2 %0, %1, %1, %0;" : "+l"(acc) : "l"(d));
}
__device__ __forceinline__ float dsum(ull acc) {
    unsigned lo, hi;
    asm("mov.b64 {%0, %1}, %2;" : "=r"(lo), "=r"(hi) : "l"(acc));
    return __uint_as_float(lo) + __uint_as_float(hi);
}

// Shared-memory union: dist stage (17KB) vs consumer tables (7.7KB) vs sort.
struct SmemDist { float2 sA[64][33]; float2 sB[64][33]; };
struct SmemScan {
    float E[NN]; float L[NN]; float ys[NN];
    float P0[NN + 1]; float P1[NN + 1]; int cnt[NN + 1];
};
union SmemU { SmemDist d; SmemScan s; float y[NN]; };

// ---------------------------------------------------------------------------
// ONE launch, 522 blocks:
//  blocks 0..199  : half-K distance producers. Block 2*tile+s computes the
//                   K-slice s (128 dims) of 32x32 tile `tile` and stores raw
//                   partial d^2 to g_D{s} — ONE staging round, half the
//                   dependent-chain of the full-K version. Math identical to
//                   the R15/R16 s-loop (same FFMA2 sequence, split at the
//                   same chunk boundary); each slice's diag partial is
//                   exactly +0. Publishes g_rflag[tile_row].
//  blocks 200,201 : exact rank sort + run bounds + zero g_S/g_C; g_sflag.
//  blocks 202..521: consumer i = b-202. Waits for sort + its tile-row's 20
//                   slice-blocks (epoch from monotone ticket), combines
//                   d2 = D0+D1 (fixed order -> deterministic; diag +0 exact,
//                   matching the reference's no-op row-max), computes
//                   L/E in smem, scans class-split prefixes, and thread k
//                   emits logp(i,k) into per-anchor atomics. 320th finisher
//                   computes the final scalar.
// Residency: smem 34KB -> 6/SM; 320 thr -> 6/SM; 522 <= 888 resident.
// ---------------------------------------------------------------------------
__global__ void __launch_bounds__(320, 3)
fused_all(const float* __restrict__ F,
          const float* __restrict__ yt,
          const int* __restrict__ ye,
          float* __restrict__ out) {
    __shared__ SmemU sm;
    __shared__ float ws0[10], ws1[10], wo0[10], wo1[10];
    __shared__ int   wsi[10], woi[10];
    __shared__ int   s_rb[7];
    __shared__ float rS[10], rC[10];
    __shared__ int   s_last;

    int b = blockIdx.x;
    int t = threadIdx.x;          // 0..319
    int lane = t & 31, w = t >> 5;

    if (b < 200) {
        // ==================== half-K dist producer ====================
        int tile = b >> 1, s = b & 1;
        bool act = (t < 256);
        int row = t >> 3;             // 0..31 (t<256)
        int col0 = (t & 7) << 4;      // 0,16,...,112 floats in this 128-chunk
        int tx = t & 15, ty = (t >> 4) & 15;
        int bi = (tile / 10) * 32, bj = (tile % 10) * 32;
        ull a00 = 0ull, a01 = 0ull, a10 = 0ull, a11 = 0ull;

        if (act) {
            const float* pA = F + (bi + row) * DD + s * 128 + col0;
            const float* pB = F + (bj + row) * DD + s * 128 + col0;
#pragma unroll
            for (int q = 0; q < 4; q++) {
                float4 av = *(const float4*)(pA + 4 * q);
                float4 bv = *(const float4*)(pB + 4 * q);
                int dp = (col0 + 4 * q) >> 1;
                sm.d.sA[dp][row]     = make_float2(av.x, av.y);
                sm.d.sA[dp + 1][row] = make_float2(av.z, av.w);
                sm.d.sB[dp][row]     = make_float2(-bv.x, -bv.y);
                sm.d.sB[dp + 1][row] = make_float2(-bv.z, -bv.w);
            }
        }
        __syncthreads();
        if (act) {
#pragma unroll 16
            for (int dd = 0; dd < 64; dd++) {
                ull x0 = *(const ull*)&sm.d.sA[dd][2 * ty];
                ull x1 = *(const ull*)&sm.d.sA[dd][2 * ty + 1];
                ull y0 = *(const ull*)&sm.d.sB[dd][2 * tx];
                ull y1 = *(const ull*)&sm.d.sB[dd][2 * tx + 1];
                dsq_acc(a00, x0, y0);
                dsq_acc(a01, x0, y1);
                dsq_acc(a10, x1, y0);
                dsq_acc(a11, x1, y1);
            }
            int i0 = bi + 2 * ty, j0 = bj + 2 * tx;
            float* D = s ? g_D1 : g_D0;
            D[i0 * NN + j0]           = dsum(a00);
            D[i0 * NN + j0 + 1]       = dsum(a01);
            D[(i0 + 1) * NN + j0]     = dsum(a10);
            D[(i0 + 1) * NN + j0 + 1] = dsum(a11);
        }
        __threadfence();
        __syncthreads();
        if (t == 0) atomicAdd(&g_rflag[tile / 10], 1);   // monotone: +20/row/replay
        return;
    }

    if (b < 202) {
        // ==================== sort / bounds producer ====================
        sm.y[t] = yt[t];
        __syncthreads();
        if (t < 160) {
            int e = (b - 200) * 160 + t;
            float v = sm.y[e];
            int rank = 0, gt = 0, geq = 0;
#pragma unroll 8
            for (int j = 0; j < NN; j++) {
                float wv = sm.y[j];
                float d = wv - v;                        // same float expr as reference pld
                rank += (wv < v) || (wv == v && j < e);  // unique tie-broken rank
                gt  += !(d > 0.0f);
                geq += (d < 0.0f);
            }
            g_ys[rank] = v; g_perm[rank] = e; g_se[rank] = __ldg(&ye[e]);
            g_gt[e] = gt; g_geq[e] = geq;
            g_S[e] = 0.f;                                // zero this replay's accumulators
            g_C[e] = 0.f;
        }
        __threadfence();
        __syncthreads();
        if (t == 0) atomicAdd(&g_sflag, 1);              // monotone: +2/replay
        return;
    }

    // ======================== consumer: row i ==========================
    int i = b - 202;

    // Wait for sort + this row's 20 slice-blocks. Epoch from monotone ticket.
    if (t == 0) {
        int ticket = atomicAdd(&g_cons, 1);
        int epoch = ticket / NN;
        int ts = (epoch + 1) * 2;
        int tr = (epoch + 1) * 20;
        while (atomicAdd(&g_sflag, 0) < ts) __nanosleep(128);
        int* rf = &g_rflag[i >> 5];
        while (atomicAdd(rf, 0) < tr) __nanosleep(128);
    }
    __syncthreads();

    // ---- Combine slices, compute L/E (producer data: __ldcg) ----
    {
        float d2 = __ldcg(&g_D0[i * NN + t]) + __ldcg(&g_D1[i * NN + t]);
        float L = -0.5f * sqrtf(d2);         // diag: +0 + +0 -> L = 0 exactly
        sm.s.L[t] = L;                       // row i of L == column i (symmetric)
        sm.s.E[t] = __expf(L);
    }
    sm.s.ys[t] = __ldcg(&g_ys[t]);
    if (t < 7) s_rb[t] = c_rb[t];
    int pj  = __ldcg(&g_perm[t]);
    int cls = __ldcg(&g_se[t]);
    __syncthreads();

    // ---- Class-split prefix scan of row i over sorted-j (eye folded) ----
    float Ev = (pj == i) ? 0.f : sm.s.E[pj];
    float x0 = cls ? 0.f : Ev;
    float x1 = cls ? Ev : 0.f;
    int   xc = cls ? (1 << 10) : 1;
#pragma unroll
    for (int off = 1; off < 32; off <<= 1) {
        float a0 = __shfl_up_sync(0xffffffffu, x0, off);
        float a1 = __shfl_up_sync(0xffffffffu, x1, off);
        int   ac = __shfl_up_sync(0xffffffffu, xc, off);
        if (lane >= off) { x0 += a0; x1 += a1; xc += ac; }
    }
    if (lane == 31) { ws0[w] = x0; ws1[w] = x1; wsi[w] = xc; }
    __syncthreads();
    if (t == 0) {
        float r0 = 0.f, r1 = 0.f; int ri = 0;
#pragma unroll
        for (int q = 0; q < 10; q++) {
            wo0[q] = r0; wo1[q] = r1; woi[q] = ri;
            r0 += ws0[q]; r1 += ws1[q]; ri += wsi[q];
        }
    }
    __syncthreads();
    sm.s.P0[t + 1]  = x0 + wo0[w];
    sm.s.P1[t + 1]  = x1 + wo1[w];
    sm.s.cnt[t + 1] = xc + woi[w];
    if (t == 0) { sm.s.P0[0] = 0.f; sm.s.P1[0] = 0.f; sm.s.cnt[0] = 0; }
    __syncthreads();

    // ---- Thread k: logp(i,k) straight from smem prefixes ----
    {
        int k = t;
        float yk = __ldg(&yt[k]);
        int   ek = __ldg(&ye[k]);
        int   gt = __ldcg(&g_gt[k]), geq = __ldcg(&g_geq[k]);
        float yi = __ldg(&yt[i]);
        int   ei = __ldg(&ye[i]);

        float pi = yi - yk;                  // reference pld for element i, anchor k
        float a = fabsf(pi), na = -a;

        int base = ei + 10 * ek;
        int cid = (pi > 0.f) ? base : ((pi < 0.f) ? -base : 0);
        int cidx = (cid == -11) ? 0 : (cid == -10) ? 1 : (cid == -1) ? 2 :
                   (cid == 0)   ? 3 : (cid == 1)   ? 4 : (cid == 10) ? 5 : 6;
        int rb = s_rb[cidx];

        // Branchless fixed-step lower bounds, interleaved. Monotone predicates
        // with the identical float expressions as the reference -> exact
        // indices. hi: first m with ys[m]-yk > a; lo: first m !(ys[m]-yk < -a).
        int hi = 0, lo = 0;
#pragma unroll
        for (int step = 256; step > 0; step >>= 1) {
            int ph = hi + step;
            int pl = lo + step;
            bool okh = (ph <= NN) && !(sm.s.ys[ph - 1] - yk > a);
            bool okl = (pl <= NN) && (sm.s.ys[pl - 1] - yk < na);
            if (okh) hi = ph;
            if (okl) lo = pl;
        }

        float SU0 = sm.s.P0[NN] - sm.s.P0[hi], SU1 = sm.s.P1[NN] - sm.s.P1[hi];
        float SL0 = sm.s.P0[lo],               SL1 = sm.s.P1[lo];
        float SM0 = (sm.s.P0[hi] - sm.s.P0[lo]) - (sm.s.P0[gt] - sm.s.P0[geq]);
        float SM1 = (sm.s.P1[hi] - sm.s.P1[lo]) - (sm.s.P1[gt] - sm.s.P1[geq]);

        float w10 = (float)((rb >> 2)  & 3), w20 = (float)((rb >> 4)  & 3), w30 = (float)((rb >> 6)  & 3);
        float w11 = (float)((rb >> 8)  & 3), w21 = (float)((rb >> 10) & 3), w31 = (float)((rb >> 12) & 3);
        float denom = 0.5f * (w10 * SL0 + w11 * SL1 + w20 * SM0 + w21 * SM1 + w30 * SU0 + w31 * SU1);

        // Exact integer validity: counts of positive-weight elements.
        int cU = sm.s.cnt[NN] - sm.s.cnt[hi];
        int cL = sm.s.cnt[lo];
        int cM = (sm.s.cnt[hi] - sm.s.cnt[lo]) - (sm.s.cnt[gt] - sm.s.cnt[geq]);
        if (pi != 0.f) cM -= (ei ? (1 << 10) : 1);   // element i sits in middle (eye)
        int nz = rb | (rb >> 1);
        int vsum = ((nz >> 2) & 1) * (cL & 1023) + ((nz >> 8)  & 1) * (cL >> 10)
                 + ((nz >> 4) & 1) * (cM & 1023) + ((nz >> 10) & 1) * (cM >> 10)
                 + ((nz >> 6) & 1) * (cU & 1023) + ((nz >> 12) & 1) * (cU >> 10);
        bool valid = (vsum > 0) && (i != k);

        if (valid) {
            float res = sm.s.L[t] - __logf(denom);   // L[i][k]
            atomicAdd(&g_S[k], res);
            atomicAdd(&g_C[k], 1.f);
        }
    }

    // ---- Completion: 320th consumer computes all loss_k + final scalar ----
    __threadfence();
    __syncthreads();
    if (t == 0) {
        int old = atomicAdd(&g_ctr, 1);
        s_last = ((old % NN) == NN - 1);   // monotone: no reset across replays
    }
    __syncthreads();
    if (s_last) {
        float S = __ldcg(&g_S[t]);
        float C = __ldcg(&g_C[t]);
        float lk = (C > 0.f) ? (-S / C) : 0.f;
        float hp = (C > 0.f) ? 1.f : 0.f;
#pragma unroll
        for (int sh = 16; sh > 0; sh >>= 1) {
            lk += __shfl_xor_sync(0xffffffffu, lk, sh);
            hp += __shfl_xor_sync(0xffffffffu, hp, sh);
        }
        if (lane == 0) { rS[w] = lk; rC[w] = hp; }
        __syncthreads();
        if (t == 0) {
            float S2 = 0.f, P2 = 0.f;
#pragma unroll
            for (int q = 0; q < 10; q++) { S2 += rS[q]; P2 += rC[q]; }
            out[0] = S2 / P2;
        }
    }
}

extern "C" void kernel_launch(void* const* d_in, const int* in_sizes, int n_in,
                              void* d_out, int out_size) {
    const float* features = (const float*)d_in[0];   // [320, 256] f32
    const float* y_times  = (const float*)d_in[1];   // [320] f32
    const int*   y_events = (const int*)d_in[2];     // [320] i32
    float* out = (float*)d_out;

    fused_all<<<NB, 320>>>(features, y_times, y_events, out);
}